// round 4
// baseline (speedup 1.0000x reference)
#include <cuda_runtime.h>
#include <cstdint>

// ---------------- problem constants ----------------
#define BB   16
#define TT   34
#define TP   32          // T - DIL
#define NN   1000
#define CIN  32
#define DC   32
#define OC   64
#define EE   16000
#define NNZ  (EE + NN)   // edges + self loops = 17000
#define GG   (BB * TP)   // 512 graphs

#define OUT1_ELEMS ((size_t)BB * DC * NN * TP)        // 16,384,000
// y elems = B*TP*N*OC = 32,768,000

// ---------------- device scratch ----------------
__device__ float g_xw[(size_t)GG * NN * DC];   // 65.5 MB
__device__ float g_deg[NN];
__device__ int   g_cnt[NN];
__device__ int   g_off[NN + 1];
__device__ int   g_cur[NN];
__device__ int   g_csr_src[NNZ];
__device__ float g_csr_val[NNZ];

// ---------------- K0: zero deg/cnt ----------------
__global__ void k_zero() {
    int i = blockIdx.x * blockDim.x + threadIdx.x;
    if (i < NN) { g_deg[i] = 0.f; g_cnt[i] = 0; }
}

// ---------------- K1: degree + row counts ----------------
__global__ void k_degcnt(const int* __restrict__ ei, const float* __restrict__ ew) {
    int i = blockIdx.x * blockDim.x + threadIdx.x;
    if (i >= NNZ) return;
    int d; float w;
    if (i < EE) { d = ei[EE + i]; w = ew[i]; }
    else        { d = i - EE;     w = 1.f;   }
    atomicAdd(&g_deg[d], w);
    atomicAdd(&g_cnt[d], 1);
}

// ---------------- K2: exclusive scan (N=1000, 1 block) ----------------
__global__ void k_scan() {
    __shared__ int s[1024];
    int i = threadIdx.x;
    int v = (i < NN) ? g_cnt[i] : 0;
    s[i] = v;
    __syncthreads();
    for (int off = 1; off < 1024; off <<= 1) {
        int tv = (i >= off) ? s[i - off] : 0;
        __syncthreads();
        s[i] += tv;
        __syncthreads();
    }
    int incl = s[i];
    if (i < NN) {
        int excl = incl - v;
        g_off[i] = excl;
        g_cur[i] = excl;
    }
    if (i == NN - 1) g_off[NN] = incl;
}

// ---------------- K3: fill CSR with normalized values ----------------
__global__ void k_fill(const int* __restrict__ ei, const float* __restrict__ ew) {
    int i = blockIdx.x * blockDim.x + threadIdx.x;
    if (i >= NNZ) return;
    int s, d; float w;
    if (i < EE) { s = ei[i]; d = ei[EE + i]; w = ew[i]; }
    else        { s = i - EE; d = s;         w = 1.f;   }
    float degs = g_deg[s], degd = g_deg[d];
    float dis_s = (degs > 0.f) ? rsqrtf(degs) : 0.f;
    float dis_d = (degd > 0.f) ? rsqrtf(degd) : 0.f;
    float nrm = dis_s * w * dis_d;
    int p = atomicAdd(&g_cur[d], 1);
    g_csr_src[p] = s;
    g_csr_val[p] = nrm;
}

// ---------------- K4: fused gated dilated conv + xw = gated @ w_gcn^T ----------------
// One 32x32 block per (b, n). Phase 1: thread (t=tx, o=ty) computes both gate
// pre-activations (weight reads are warp-broadcasts, x reads lane-consecutive),
// applies tanh*sigmoid, writes out1 coalesced along t. Phase 2: thread
// (c=tx, t=ty) computes xw with coalesced stores along c.
__global__ __launch_bounds__(1024) void k_gate(
    const float* __restrict__ x,
    const float* __restrict__ wg1, const float* __restrict__ bg1,
    const float* __restrict__ wg2, const float* __restrict__ bg2,
    const float* __restrict__ wgcn,
    float* __restrict__ out1)
{
    int blk = blockIdx.x;
    int b = blk / NN;
    int n = blk - b * NN;

    __shared__ float4 xq[8][34];                 // [c4][t]  x[t][4c4..4c4+3]
    __shared__ float4 w1a[32][8], w1b[32][8];    // [o][c4]
    __shared__ float4 w2a[32][8], w2b[32][8];
    __shared__ float4 wgq[8][32];                // [d4][c]  w_gcn[c][4d4..4d4+3]
    __shared__ float  gs[32 * 36];               // gated [t][d], pitch 36

    int tid = threadIdx.y * 32 + threadIdx.x;

    // stage weights (flat float index of [o][c4] float4 arrays == o*32+c)
    {
        ((float*)w1a)[tid] = wg1[tid * 2];
        ((float*)w1b)[tid] = wg1[tid * 2 + 1];
        ((float*)w2a)[tid] = wg2[tid * 2];
        ((float*)w2b)[tid] = wg2[tid * 2 + 1];
        int k = tid & 3, cc = (tid >> 2) & 31, d4 = tid >> 7;
        ((float*)wgq)[tid] = wgcn[cc * 32 + 4 * d4 + k];
    }
    // stage x tile: 34 rows x 8 float4
    if (tid < 34 * 8) {
        int t = tid >> 3, c4 = tid & 7;
        xq[c4][t] = *(const float4*)(x + ((size_t)(b * TT + t) * NN + n) * CIN + c4 * 4);
    }
    __syncthreads();

    // ---- phase 1: gates ----
    {
        int t = threadIdx.x, o = threadIdx.y;
        float a1 = __ldg(bg1 + o);
        float a2 = __ldg(bg2 + o);
#pragma unroll
        for (int c4 = 0; c4 < 8; c4++) {
            float4 xa = xq[c4][t];
            float4 xb = xq[c4][t + 2];
            float4 A1 = w1a[o][c4], B1 = w1b[o][c4];
            float4 A2 = w2a[o][c4], B2 = w2b[o][c4];
            a1 += xa.x*A1.x + xa.y*A1.y + xa.z*A1.z + xa.w*A1.w
                + xb.x*B1.x + xb.y*B1.y + xb.z*B1.z + xb.w*B1.w;
            a2 += xa.x*A2.x + xa.y*A2.y + xa.z*A2.z + xa.w*A2.w
                + xb.x*B2.x + xb.y*B2.y + xb.z*B2.z + xb.w*B2.w;
        }
        float e1 = __expf(2.f * a1);
        float th = 1.f - __fdividef(2.f, e1 + 1.f);           // tanh, inf-safe
        float sg = __fdividef(1.f, 1.f + __expf(-a2));        // sigmoid
        float gated = th * sg;
        out1[((size_t)(b * DC + o) * NN + n) * TP + t] = gated;   // [B,DC,N,TP]
        gs[t * 36 + o] = gated;
    }
    __syncthreads();

    // ---- phase 2: xw[g,n,c] = sum_d gated[t][d] * w_gcn[c][d] ----
    {
        int c = threadIdx.x, t = threadIdx.y;
        float acc = 0.f;
#pragma unroll
        for (int d4 = 0; d4 < 8; d4++) {
            float4 g4 = *(float4*)(gs + t * 36 + d4 * 4);  // warp-broadcast, 16B aligned
            float4 w4 = wgq[d4][c];
            acc += g4.x*w4.x + g4.y*w4.y + g4.z*w4.z + g4.w*w4.w;
        }
        g_xw[((size_t)(b * TP + t) * NN + n) * DC + c] = acc;
    }
}

// ---------------- K5: fused GCN SpMM + 1x1 out conv ----------------
// One block per graph g (512 blocks). xw[g] (128KB) staged in dynamic SMEM so
// the edge gather hits SMEM. Warp w handles rows i = w, w+32, ...
// lane = channel c for the gather; then shfl-based 32->64 GEMV for y.
#define K5_SMEM_FLOATS (NN * DC + 8 * OC * 4)   // xw slab + w_out as float4 [c4][o]
__global__ __launch_bounds__(1024, 1) void k_spmm(
    const float* __restrict__ bgcn,
    const float* __restrict__ wout,
    const float* __restrict__ bout,
    float* __restrict__ y)
{
    extern __shared__ float smem[];
    float*  xw_s = smem;                       // [N][DC]
    float4* woT  = (float4*)(smem + NN * DC);  // [c4][o] -> w_out[o][4c4..4c4+3]

    int g   = blockIdx.x;
    int tid = threadIdx.x;

    // stage xw[g] slab
    const float4* src4 = (const float4*)(g_xw + (size_t)g * NN * DC);
    for (int idx = tid; idx < NN * DC / 4; idx += 1024)
        ((float4*)xw_s)[idx] = src4[idx];
    // stage w_out: flat float index f = (c4*OC+o)*4+k
    for (int f = tid; f < 8 * OC * 4; f += 1024) {
        int k = f & 3, o = (f >> 2) & 63, c4 = f >> 8;
        ((float*)woT)[f] = wout[o * 32 + c4 * 4 + k];
    }
    __syncthreads();

    int warp = tid >> 5;
    int lane = tid & 31;
    float bg  = __ldg(bgcn + lane);
    float boA = __ldg(bout + lane);
    float boB = __ldg(bout + lane + 32);

    for (int i = warp; i < NN; i += 32) {
        int r0 = g_off[i], r1 = g_off[i + 1];
        float acc = bg;                        // gcn[g,i,lane]
        for (int e0 = r0; e0 < r1; e0 += 32) {
            int ee = e0 + lane;
            int   js = 0;
            float vs = 0.f;
            if (ee < r1) { js = g_csr_src[ee]; vs = g_csr_val[ee]; }
            int cnt = min(32, r1 - e0);
            for (int k = 0; k < cnt; k++) {
                int   jj = __shfl_sync(0xffffffffu, js, k);
                float vv = __shfl_sync(0xffffffffu, vs, k);
                acc += vv * xw_s[jj * DC + lane];
            }
        }
        // y[g,i,o] = sum_c gcn[c] * w_out[o][c] + b_out[o]
        float ya = boA, yb = boB;
#pragma unroll
        for (int c4 = 0; c4 < 8; c4++) {
            float g0 = __shfl_sync(0xffffffffu, acc, 4 * c4 + 0);
            float g1 = __shfl_sync(0xffffffffu, acc, 4 * c4 + 1);
            float g2 = __shfl_sync(0xffffffffu, acc, 4 * c4 + 2);
            float g3 = __shfl_sync(0xffffffffu, acc, 4 * c4 + 3);
            float4 wA = woT[c4 * OC + lane];
            float4 wB = woT[c4 * OC + lane + 32];
            ya += g0*wA.x + g1*wA.y + g2*wA.z + g3*wA.w;
            yb += g0*wB.x + g1*wB.y + g2*wB.z + g3*wB.w;
        }
        float* yo = y + ((size_t)g * NN + i) * OC;
        yo[lane]      = ya;
        yo[lane + 32] = yb;
    }
}

// ---------------- launcher ----------------
extern "C" void kernel_launch(void* const* d_in, const int* in_sizes, int n_in,
                              void* d_out, int out_size)
{
    const float* x    = (const float*)d_in[0];
    const int*   ei   = (const int*)  d_in[1];
    const float* ew   = (const float*)d_in[2];
    const float* wg1  = (const float*)d_in[3];
    const float* bg1  = (const float*)d_in[4];
    const float* wg2  = (const float*)d_in[5];
    const float* bg2  = (const float*)d_in[6];
    const float* wgcn = (const float*)d_in[7];
    const float* bgcn = (const float*)d_in[8];
    const float* wout = (const float*)d_in[9];
    const float* bout = (const float*)d_in[10];
    float* out = (float*)d_out;

    // CSR build (shared adjacency for all graphs)
    k_zero  <<<(NN  + 255) / 256, 256>>>();
    k_degcnt<<<(NNZ + 255) / 256, 256>>>(ei, ew);
    k_scan  <<<1, 1024>>>();
    k_fill  <<<(NNZ + 255) / 256, 256>>>(ei, ew);

    // fused gates + xw
    k_gate<<<BB * NN, dim3(32, 32)>>>(x, wg1, bg1, wg2, bg2, wgcn, out);

    // fused SpMM + out conv
    size_t smem_bytes = (size_t)K5_SMEM_FLOATS * sizeof(float);
    cudaFuncSetAttribute(k_spmm, cudaFuncAttributeMaxDynamicSharedMemorySize,
                         (int)smem_bytes);
    k_spmm<<<GG, 1024, smem_bytes>>>(bgcn, wout, bout, out + OUT1_ELEMS);
}

// round 8
// speedup vs baseline: 1.3720x; 1.3720x over previous
#include <cuda_runtime.h>
#include <cstdint>

// ---------------- problem constants ----------------
#define BB   16
#define TT   34
#define TP   32          // T - DIL
#define NN   1000
#define CIN  32
#define DC   32
#define OC   64
#define EE   16000
#define NNZ  (EE + NN)   // edges + self loops = 17000
#define GG   (BB * TP)   // 512 graphs

#define OUT1_ELEMS ((size_t)BB * DC * NN * TP)        // 16,384,000

typedef unsigned long long u64c;

// ---------------- f32x2 packed helpers ----------------
__device__ __forceinline__ u64c fma2(u64c a, u64c b, u64c c) {
    u64c d;
    asm("fma.rn.f32x2 %0, %1, %2, %3;" : "=l"(d) : "l"(a), "l"(b), "l"(c));
    return d;
}
__device__ __forceinline__ float f2sum(u64c a) {
    return __int_as_float((int)(a & 0xffffffffULL)) +
           __int_as_float((int)(a >> 32));
}

// ---------------- device scratch ----------------
__device__ float g_z[(size_t)GG * NN * OC];   // 131 MB: z = gated @ Wcomb^T
__device__ float g_wcomb[OC * DC];            // Wcomb[o][d] = sum_c wout[o][c] wgcn[c][d]
__device__ float g_ybias[OC];                 // bgcn @ wout^T + bout
__device__ float g_deg[NN];
__device__ int   g_cnt[NN];
__device__ int   g_off[NN + 1];
__device__ int   g_cur[NN];
__device__ int2  g_csr[NNZ];                  // (src*128 byte offset, f32 val as int)

// ---------------- K0: zero deg/cnt ----------------
__global__ void k_zero() {
    int i = blockIdx.x * blockDim.x + threadIdx.x;
    if (i < NN) { g_deg[i] = 0.f; g_cnt[i] = 0; }
}

// ---------------- K1: degree + row counts ----------------
__global__ void k_degcnt(const int* __restrict__ ei, const float* __restrict__ ew) {
    int i = blockIdx.x * blockDim.x + threadIdx.x;
    if (i >= NNZ) return;
    int d; float w;
    if (i < EE) { d = ei[EE + i]; w = ew[i]; }
    else        { d = i - EE;     w = 1.f;   }
    atomicAdd(&g_deg[d], w);
    atomicAdd(&g_cnt[d], 1);
}

// ---------------- K2: exclusive scan (N=1000, 1 block) ----------------
__global__ void k_scan() {
    __shared__ int s[1024];
    int i = threadIdx.x;
    int v = (i < NN) ? g_cnt[i] : 0;
    s[i] = v;
    __syncthreads();
    for (int off = 1; off < 1024; off <<= 1) {
        int tv = (i >= off) ? s[i - off] : 0;
        __syncthreads();
        s[i] += tv;
        __syncthreads();
    }
    int incl = s[i];
    if (i < NN) {
        int excl = incl - v;
        g_off[i] = excl;
        g_cur[i] = excl;
    }
    if (i == NN - 1) g_off[NN] = incl;
}

// ---------------- K3: fill packed CSR with normalized values ----------------
__global__ void k_fill(const int* __restrict__ ei, const float* __restrict__ ew) {
    int i = blockIdx.x * blockDim.x + threadIdx.x;
    if (i >= NNZ) return;
    int s, d; float w;
    if (i < EE) { s = ei[i]; d = ei[EE + i]; w = ew[i]; }
    else        { s = i - EE; d = s;         w = 1.f;   }
    float degs = g_deg[s], degd = g_deg[d];
    float dis_s = (degs > 0.f) ? rsqrtf(degs) : 0.f;
    float dis_d = (degd > 0.f) ? rsqrtf(degd) : 0.f;
    float nrm = dis_s * w * dis_d;
    int p = atomicAdd(&g_cur[d], 1);
    g_csr[p] = make_int2(s * 128, __float_as_int(nrm));  // 128 = 32 floats/row slab
}

// ---------------- K3b: combined weights (propagate/conv commute) ----------------
__global__ void k_comb(const float* __restrict__ wgcn, const float* __restrict__ bgcn,
                       const float* __restrict__ wout, const float* __restrict__ bout) {
    __shared__ float sg[CIN * DC];   // wgcn [c][d]
    __shared__ float so[OC * CIN];   // wout [o][c]
    __shared__ float sb[CIN];
    int tid = threadIdx.x;
    for (int f = tid; f < CIN * DC; f += blockDim.x) sg[f] = wgcn[f];
    for (int f = tid; f < OC * CIN; f += blockDim.x) so[f] = wout[f];
    if (tid < CIN) sb[tid] = bgcn[tid];
    __syncthreads();
    for (int f = tid; f < OC * DC; f += blockDim.x) {
        int o = f >> 5, d = f & 31;
        float s = 0.f;
#pragma unroll
        for (int c = 0; c < CIN; c++) s += so[o * CIN + c] * sg[c * DC + d];
        g_wcomb[f] = s;
    }
    if (tid < OC) {
        float s = bout[tid];
#pragma unroll
        for (int c = 0; c < CIN; c++) s += sb[c] * so[tid * CIN + c];
        g_ybias[tid] = s;
    }
}

// ---------------- K4: fused gated dilated conv + z = gated @ Wcomb^T ----------------
// One 256-thread block per (b, n). Phase 1: warp wy covers o in {4wy..4wy+3},
// t = lane; 4-way o register blocking reuses each x read 4x; all inner FMAs
// are packed fma.rn.f32x2 over c-pairs. Phase 2: thread (o = tid&63,
// ts = tid>>6) computes z[t][o] for t = ts*8+it with Wcomb row cached in regs.
__global__ __launch_bounds__(256) void k_gate(
    const float* __restrict__ x,
    const float* __restrict__ wg1, const float* __restrict__ bg1,
    const float* __restrict__ wg2, const float* __restrict__ bg2,
    float* __restrict__ out1)
{
    int blk = blockIdx.x;
    int b = blk / NN;
    int n = blk - b * NN;

    __shared__ float4 xq[8][34];                 // [c4][t]  x[t][4c4..4c4+3]
    __shared__ float4 w1a[32][8], w1b[32][8];    // [o][c4]
    __shared__ float4 w2a[32][8], w2b[32][8];
    __shared__ float4 wcq[8][64];                // [d4][o]  Wcomb[o][4d4..4d4+3]
    __shared__ float  gs[32 * 36];               // gated [t][d], pitch 36

    int tx = threadIdx.x;            // 0..31
    int wy = threadIdx.y;            // 0..7
    int tid = wy * 32 + tx;

    // stage gate weights: each array is 32*32 floats (flat f = o*32+c).
    // (R5 bug: this was a single per-thread store covering only f<256.)
    for (int f = tid; f < 32 * 32; f += 256) {
        ((float*)w1a)[f] = wg1[f * 2];
        ((float*)w1b)[f] = wg1[f * 2 + 1];
        ((float*)w2a)[f] = wg2[f * 2];
        ((float*)w2b)[f] = wg2[f * 2 + 1];
    }
    // stage Wcomb: flat f = (d4*64+o)*4+k  <-  wcomb[o*32 + d4*4 + k]
    for (int f = tid; f < 8 * 64 * 4; f += 256) {
        int k = f & 3, o = (f >> 2) & 63, d4 = f >> 8;
        ((float*)wcq)[f] = g_wcomb[o * 32 + d4 * 4 + k];
    }
    // stage x tile: 34 rows x 8 float4
    for (int f = tid; f < 34 * 8; f += 256) {
        int t = f >> 3, c4 = f & 7;
        xq[c4][t] = *(const float4*)(x + ((size_t)(b * TT + t) * NN + n) * CIN + c4 * 4);
    }
    __syncthreads();

    // ---- phase 1: gates (t = tx, o = 4*wy + oo) ----
    {
        int t = tx;
        u64c a1[4] = {0, 0, 0, 0};
        u64c a2[4] = {0, 0, 0, 0};
#pragma unroll
        for (int c4 = 0; c4 < 8; c4++) {
            ulonglong2 xa = *(const ulonglong2*)&xq[c4][t];
            ulonglong2 xb = *(const ulonglong2*)&xq[c4][t + 2];
#pragma unroll
            for (int oo = 0; oo < 4; oo++) {
                int o = 4 * wy + oo;
                ulonglong2 A1 = *(const ulonglong2*)&w1a[o][c4];
                ulonglong2 B1 = *(const ulonglong2*)&w1b[o][c4];
                ulonglong2 A2 = *(const ulonglong2*)&w2a[o][c4];
                ulonglong2 B2 = *(const ulonglong2*)&w2b[o][c4];
                a1[oo] = fma2(xa.x, A1.x, a1[oo]);
                a1[oo] = fma2(xa.y, A1.y, a1[oo]);
                a1[oo] = fma2(xb.x, B1.x, a1[oo]);
                a1[oo] = fma2(xb.y, B1.y, a1[oo]);
                a2[oo] = fma2(xa.x, A2.x, a2[oo]);
                a2[oo] = fma2(xa.y, A2.y, a2[oo]);
                a2[oo] = fma2(xb.x, B2.x, a2[oo]);
                a2[oo] = fma2(xb.y, B2.y, a2[oo]);
            }
        }
#pragma unroll
        for (int oo = 0; oo < 4; oo++) {
            int o = 4 * wy + oo;
            float s1 = f2sum(a1[oo]) + __ldg(bg1 + o);
            float s2 = f2sum(a2[oo]) + __ldg(bg2 + o);
            float e1 = __expf(2.f * s1);
            float th = 1.f - __fdividef(2.f, e1 + 1.f);        // tanh, inf-safe
            float sg = __fdividef(1.f, 1.f + __expf(-s2));     // sigmoid
            float gated = th * sg;
            out1[((size_t)(b * DC + o) * NN + n) * TP + t] = gated;  // [B,DC,N,TP]
            gs[t * 36 + o] = gated;
        }
    }
    __syncthreads();

    // ---- phase 2: z[t][o] = sum_d gated[t][d] * Wcomb[o][d] ----
    {
        int o  = tid & 63;
        int ts = tid >> 6;          // 0..3
        ulonglong2 wr[8];
#pragma unroll
        for (int d4 = 0; d4 < 8; d4++)
            wr[d4] = *(const ulonglong2*)&wcq[d4][o];
#pragma unroll
        for (int it = 0; it < 8; it++) {
            int t = ts * 8 + it;
            const ulonglong2* gp = (const ulonglong2*)(gs + t * 36);
            u64c za = 0, zb = 0;
#pragma unroll
            for (int d4 = 0; d4 < 8; d4++) {
                ulonglong2 g2 = gp[d4];
                za = fma2(g2.x, wr[d4].x, za);
                zb = fma2(g2.y, wr[d4].y, zb);
            }
            g_z[((size_t)(b * TP + t) * NN + n) * OC + o] = f2sum(za) + f2sum(zb);
        }
    }
}

// ---------------- K5: pure gather  y[g,i,o] = sum_e val*z[src,o] + ybias[o] ----
// 1024 blocks = (graph g, channel-half). z half-slab (1000x32 = 128 KB) staged
// in dynamic SMEM; per edge: one uniform LDG.64 of (byte_off, val) + LDS + FFMA.
__global__ __launch_bounds__(1024, 1) void k_spmm(float* __restrict__ y)
{
    extern __shared__ float z_s[];            // [N][32]
    int bx = blockIdx.x;
    int g = bx >> 1, half = bx & 1;
    int tid = threadIdx.x;

    for (int f = tid; f < NN * 8; f += 1024) {
        int n = f >> 3, c4 = f & 7;
        ((float4*)z_s)[f] =
            *(const float4*)(g_z + ((size_t)g * NN + n) * OC + half * 32 + c4 * 4);
    }
    __syncthreads();

    int warp = tid >> 5;
    int lane = tid & 31;
    float yb = __ldg(&g_ybias[half * 32 + lane]);
    const char* zbase = (const char*)z_s + lane * 4;

    for (int i = warp; i < NN; i += 32) {
        int r0 = g_off[i], r1 = g_off[i + 1];
        float acc = yb;
#pragma unroll 4
        for (int e = r0; e < r1; e++) {
            int2 ev = __ldg(&g_csr[e]);       // uniform across warp
            acc += __int_as_float(ev.y) * *(const float*)(zbase + ev.x);
        }
        y[((size_t)g * NN + i) * OC + half * 32 + lane] = acc;
    }
}

// ---------------- launcher ----------------
extern "C" void kernel_launch(void* const* d_in, const int* in_sizes, int n_in,
                              void* d_out, int out_size)
{
    const float* x    = (const float*)d_in[0];
    const int*   ei   = (const int*)  d_in[1];
    const float* ew   = (const float*)d_in[2];
    const float* wg1  = (const float*)d_in[3];
    const float* bg1  = (const float*)d_in[4];
    const float* wg2  = (const float*)d_in[5];
    const float* bg2  = (const float*)d_in[6];
    const float* wgcn = (const float*)d_in[7];
    const float* bgcn = (const float*)d_in[8];
    const float* wout = (const float*)d_in[9];
    const float* bout = (const float*)d_in[10];
    float* out = (float*)d_out;

    // CSR build (shared adjacency for all graphs) + combined weights
    k_zero  <<<(NN  + 255) / 256, 256>>>();
    k_degcnt<<<(NNZ + 255) / 256, 256>>>(ei, ew);
    k_scan  <<<1, 1024>>>();
    k_fill  <<<(NNZ + 255) / 256, 256>>>(ei, ew);
    k_comb  <<<1, 512>>>(wgcn, bgcn, wout, bout);

    // fused gates + z
    k_gate<<<BB * NN, dim3(32, 8)>>>(x, wg1, bg1, wg2, bg2, out);

    // gather
    size_t smem_bytes = (size_t)NN * 32 * sizeof(float);   // 128 KB
    cudaFuncSetAttribute(k_spmm, cudaFuncAttributeMaxDynamicSharedMemorySize,
                         (int)smem_bytes);
    k_spmm<<<2 * GG, 1024, smem_bytes>>>(out + OUT1_ELEMS);
}

// round 9
// speedup vs baseline: 1.6027x; 1.1682x over previous
#include <cuda_runtime.h>
#include <cstdint>

// ---------------- problem constants ----------------
#define BB   16
#define TT   34
#define TP   32          // T - DIL
#define NN   1000
#define CIN  32
#define DC   32
#define OC   64
#define EE   16000
#define NNZ  (EE + NN)   // edges + self loops = 17000
#define GG   (BB * TP)   // 512 graphs

#define OUT1_ELEMS ((size_t)BB * DC * NN * TP)        // 16,384,000

typedef unsigned long long u64c;

// ---------------- f32x2 packed helpers ----------------
__device__ __forceinline__ u64c fma2(u64c a, u64c b, u64c c) {
    u64c d;
    asm("fma.rn.f32x2 %0, %1, %2, %3;" : "=l"(d) : "l"(a), "l"(b), "l"(c));
    return d;
}
__device__ __forceinline__ float f2sum(u64c a) {
    return __int_as_float((int)(a & 0xffffffffULL)) +
           __int_as_float((int)(a >> 32));
}
__device__ __forceinline__ u64c pack2(float lo, float hi) {
    u64c r;
    asm("mov.b64 %0, {%1, %2};" : "=l"(r) : "f"(lo), "f"(hi));
    return r;
}
__device__ __forceinline__ float u64lo(u64c a) { return __int_as_float((int)(a & 0xffffffffULL)); }
__device__ __forceinline__ float u64hi(u64c a) { return __int_as_float((int)(a >> 32)); }

// ---------------- device scratch ----------------
__device__ float g_z[(size_t)GG * NN * OC];   // 131 MB: z = gated @ Wcomb^T
__device__ float g_wcomb[OC * DC];            // Wcomb[o][d] = sum_c wout[o][c] wgcn[c][d]
__device__ float g_ybias[OC];                 // bgcn @ wout^T + bout
__device__ float g_deg[NN];
__device__ int   g_cnt[NN];
__device__ int   g_off[NN + 1];
__device__ int   g_cur[NN];
__device__ int2  g_csr[NNZ];                  // (src*128 byte offset, f32 val as int)

// ---------------- K0: zero deg/cnt ----------------
__global__ void k_zero() {
    int i = blockIdx.x * blockDim.x + threadIdx.x;
    if (i < NN) { g_deg[i] = 0.f; g_cnt[i] = 0; }
}

// ---------------- K1: degree + row counts ----------------
__global__ void k_degcnt(const int* __restrict__ ei, const float* __restrict__ ew) {
    int i = blockIdx.x * blockDim.x + threadIdx.x;
    if (i >= NNZ) return;
    int d; float w;
    if (i < EE) { d = ei[EE + i]; w = ew[i]; }
    else        { d = i - EE;     w = 1.f;   }
    atomicAdd(&g_deg[d], w);
    atomicAdd(&g_cnt[d], 1);
}

// ---------------- K2: exclusive scan (N=1000, 1 block) ----------------
__global__ void k_scan() {
    __shared__ int s[1024];
    int i = threadIdx.x;
    int v = (i < NN) ? g_cnt[i] : 0;
    s[i] = v;
    __syncthreads();
    for (int off = 1; off < 1024; off <<= 1) {
        int tv = (i >= off) ? s[i - off] : 0;
        __syncthreads();
        s[i] += tv;
        __syncthreads();
    }
    int incl = s[i];
    if (i < NN) {
        int excl = incl - v;
        g_off[i] = excl;
        g_cur[i] = excl;
    }
    if (i == NN - 1) g_off[NN] = incl;
}

// ---------------- K3: fill packed CSR with normalized values ----------------
__global__ void k_fill(const int* __restrict__ ei, const float* __restrict__ ew) {
    int i = blockIdx.x * blockDim.x + threadIdx.x;
    if (i >= NNZ) return;
    int s, d; float w;
    if (i < EE) { s = ei[i]; d = ei[EE + i]; w = ew[i]; }
    else        { s = i - EE; d = s;         w = 1.f;   }
    float degs = g_deg[s], degd = g_deg[d];
    float dis_s = (degs > 0.f) ? rsqrtf(degs) : 0.f;
    float dis_d = (degd > 0.f) ? rsqrtf(degd) : 0.f;
    float nrm = dis_s * w * dis_d;
    int p = atomicAdd(&g_cur[d], 1);
    g_csr[p] = make_int2(s * 128, __float_as_int(nrm));  // 128 = 32 floats/row slab
}

// ---------------- K3b: combined weights (propagate/conv commute) ----------------
__global__ void k_comb(const float* __restrict__ wgcn, const float* __restrict__ bgcn,
                       const float* __restrict__ wout, const float* __restrict__ bout) {
    __shared__ float sg[CIN * DC];   // wgcn [c][d]
    __shared__ float so[OC * CIN];   // wout [o][c]
    __shared__ float sb[CIN];
    int tid = threadIdx.x;
    for (int f = tid; f < CIN * DC; f += blockDim.x) sg[f] = wgcn[f];
    for (int f = tid; f < OC * CIN; f += blockDim.x) so[f] = wout[f];
    if (tid < CIN) sb[tid] = bgcn[tid];
    __syncthreads();
    for (int f = tid; f < OC * DC; f += blockDim.x) {
        int o = f >> 5, d = f & 31;
        float s = 0.f;
#pragma unroll
        for (int c = 0; c < CIN; c++) s += so[o * CIN + c] * sg[c * DC + d];
        g_wcomb[f] = s;
    }
    if (tid < OC) {
        float s = bout[tid];
#pragma unroll
        for (int c = 0; c < CIN; c++) s += sb[c] * so[tid * CIN + c];
        g_ybias[tid] = s;
    }
}

// ---------------- K4: fused gated dilated conv + z = gated @ Wcomb^T ----------------
// One 256-thread block per (b, n). Phase 1: warp wy covers o in {4wy..4wy+3},
// t = lane; 4-way o register blocking reuses each x read 4x; all inner FMAs
// are packed fma.rn.f32x2 over c-pairs. Phase 2: thread (o = tid&63,
// ts = tid>>6) computes z[t][o] for t = ts*8+it with Wcomb row cached in regs.
__global__ __launch_bounds__(256) void k_gate(
    const float* __restrict__ x,
    const float* __restrict__ wg1, const float* __restrict__ bg1,
    const float* __restrict__ wg2, const float* __restrict__ bg2,
    float* __restrict__ out1)
{
    int blk = blockIdx.x;
    int b = blk / NN;
    int n = blk - b * NN;

    __shared__ float4 xq[8][34];                 // [c4][t]  x[t][4c4..4c4+3]
    __shared__ float4 w1a[32][8], w1b[32][8];    // [o][c4]
    __shared__ float4 w2a[32][8], w2b[32][8];
    __shared__ float4 wcq[8][64];                // [d4][o]  Wcomb[o][4d4..4d4+3]
    __shared__ float  gs[32 * 36];               // gated [t][d], pitch 36

    int tx = threadIdx.x;            // 0..31
    int wy = threadIdx.y;            // 0..7
    int tid = wy * 32 + tx;

    // stage gate weights: each array is 32*32 floats (flat f = o*32+c)
    for (int f = tid; f < 32 * 32; f += 256) {
        float2 v1 = *(const float2*)(wg1 + f * 2);
        float2 v2 = *(const float2*)(wg2 + f * 2);
        ((float*)w1a)[f] = v1.x;
        ((float*)w1b)[f] = v1.y;
        ((float*)w2a)[f] = v2.x;
        ((float*)w2b)[f] = v2.y;
    }
    // stage Wcomb: flat f = (d4*64+o)*4+k  <-  wcomb[o*32 + d4*4 + k]
    for (int f = tid; f < 8 * 64 * 4; f += 256) {
        int k = f & 3, o = (f >> 2) & 63, d4 = f >> 8;
        ((float*)wcq)[f] = g_wcomb[o * 32 + d4 * 4 + k];
    }
    // stage x tile: 34 rows x 8 float4
    for (int f = tid; f < 34 * 8; f += 256) {
        int t = f >> 3, c4 = f & 7;
        xq[c4][t] = *(const float4*)(x + ((size_t)(b * TT + t) * NN + n) * CIN + c4 * 4);
    }
    __syncthreads();

    // ---- phase 1: gates (t = tx, o = 4*wy + oo) ----
    {
        int t = tx;
        u64c a1[4] = {0, 0, 0, 0};
        u64c a2[4] = {0, 0, 0, 0};
#pragma unroll
        for (int c4 = 0; c4 < 8; c4++) {
            ulonglong2 xa = *(const ulonglong2*)&xq[c4][t];
            ulonglong2 xb = *(const ulonglong2*)&xq[c4][t + 2];
#pragma unroll
            for (int oo = 0; oo < 4; oo++) {
                int o = 4 * wy + oo;
                ulonglong2 A1 = *(const ulonglong2*)&w1a[o][c4];
                ulonglong2 B1 = *(const ulonglong2*)&w1b[o][c4];
                ulonglong2 A2 = *(const ulonglong2*)&w2a[o][c4];
                ulonglong2 B2 = *(const ulonglong2*)&w2b[o][c4];
                a1[oo] = fma2(xa.x, A1.x, a1[oo]);
                a1[oo] = fma2(xa.y, A1.y, a1[oo]);
                a1[oo] = fma2(xb.x, B1.x, a1[oo]);
                a1[oo] = fma2(xb.y, B1.y, a1[oo]);
                a2[oo] = fma2(xa.x, A2.x, a2[oo]);
                a2[oo] = fma2(xa.y, A2.y, a2[oo]);
                a2[oo] = fma2(xb.x, B2.x, a2[oo]);
                a2[oo] = fma2(xb.y, B2.y, a2[oo]);
            }
        }
#pragma unroll
        for (int oo = 0; oo < 4; oo++) {
            int o = 4 * wy + oo;
            float s1 = f2sum(a1[oo]) + __ldg(bg1 + o);
            float s2 = f2sum(a2[oo]) + __ldg(bg2 + o);
            float e1 = __expf(2.f * s1);
            float th = 1.f - __fdividef(2.f, e1 + 1.f);        // tanh, inf-safe
            float sg = __fdividef(1.f, 1.f + __expf(-s2));     // sigmoid
            float gated = th * sg;
            out1[((size_t)(b * DC + o) * NN + n) * TP + t] = gated;  // [B,DC,N,TP]
            gs[t * 36 + o] = gated;
        }
    }
    __syncthreads();

    // ---- phase 2: z[t][o] = sum_d gated[t][d] * Wcomb[o][d] ----
    {
        int o  = tid & 63;
        int ts = tid >> 6;          // 0..3
        ulonglong2 wr[8];
#pragma unroll
        for (int d4 = 0; d4 < 8; d4++)
            wr[d4] = *(const ulonglong2*)&wcq[d4][o];
#pragma unroll
        for (int it = 0; it < 8; it++) {
            int t = ts * 8 + it;
            const ulonglong2* gp = (const ulonglong2*)(gs + t * 36);
            u64c za = 0, zb = 0;
#pragma unroll
            for (int d4 = 0; d4 < 8; d4++) {
                ulonglong2 g2 = gp[d4];
                za = fma2(g2.x, wr[d4].x, za);
                zb = fma2(g2.y, wr[d4].y, zb);
            }
            g_z[((size_t)(b * TP + t) * NN + n) * OC + o] = f2sum(za) + f2sum(zb);
        }
    }
}

// ---------------- K5: pure gather  y[g,i,:] = sum_e val*z[src,:] + ybias ----
// 1024 blocks = (graph g, channel-half). z half-slab (1000x32 = 128 KB) staged
// in dynamic SMEM. Warp = 4 subgroups x 8 lanes: subgroup walks one row's edge
// list, each lane accumulates a float4 of channels as two packed fma2 chains.
// Per edge (warp serves 4 edges/iter): 1 uniform LDG.64 + 1 LDS.128
// (4 row-aligned 128B blocks, conflict-free) + 2 fma2.
__global__ __launch_bounds__(1024, 1) void k_spmm(float* __restrict__ y)
{
    extern __shared__ float z_s[];            // [N][32]
    int bx = blockIdx.x;
    int g = bx >> 1, half = bx & 1;
    int tid = threadIdx.x;

    for (int f = tid; f < NN * 8; f += 1024) {
        int n = f >> 3, c4 = f & 7;
        ((float4*)z_s)[f] =
            *(const float4*)(g_z + ((size_t)g * NN + n) * OC + half * 32 + c4 * 4);
    }
    __syncthreads();

    int warp = tid >> 5;
    int lane = tid & 31;
    int sub  = lane >> 3;                     // 0..3 row subgroup
    int c4   = lane & 7;                      // float4 channel group in half
    float4 yb4 = *(const float4*)(g_ybias + half * 32 + c4 * 4);
    const char* zb = (const char*)z_s + c4 * 16;

    for (int i0 = warp * 4 + sub; i0 < NN + 3; i0 += 128) {
        int i = i0;
        bool valid = (i < NN);
        int r0 = 0, r1 = 0;
        if (valid) { r0 = g_off[i]; r1 = g_off[i + 1]; }
        u64c a0 = pack2(yb4.x, yb4.y);
        u64c a1 = pack2(yb4.z, yb4.w);
#pragma unroll 2
        for (int e = r0; e < r1; e++) {
            int2 ev = __ldg(&g_csr[e]);       // uniform within subgroup
            float v = __int_as_float(ev.y);
            u64c vv = pack2(v, v);
            ulonglong2 zz = *(const ulonglong2*)(zb + ev.x);
            a0 = fma2(zz.x, vv, a0);
            a1 = fma2(zz.y, vv, a1);
        }
        if (valid) {
            float4 r;
            r.x = u64lo(a0); r.y = u64hi(a0);
            r.z = u64lo(a1); r.w = u64hi(a1);
            *(float4*)(y + ((size_t)g * NN + i) * OC + half * 32 + c4 * 4) = r;
        }
    }
}

// ---------------- launcher ----------------
extern "C" void kernel_launch(void* const* d_in, const int* in_sizes, int n_in,
                              void* d_out, int out_size)
{
    const float* x    = (const float*)d_in[0];
    const int*   ei   = (const int*)  d_in[1];
    const float* ew   = (const float*)d_in[2];
    const float* wg1  = (const float*)d_in[3];
    const float* bg1  = (const float*)d_in[4];
    const float* wg2  = (const float*)d_in[5];
    const float* bg2  = (const float*)d_in[6];
    const float* wgcn = (const float*)d_in[7];
    const float* bgcn = (const float*)d_in[8];
    const float* wout = (const float*)d_in[9];
    const float* bout = (const float*)d_in[10];
    float* out = (float*)d_out;

    // Launch order chosen so k_gate sits at the profiler's capture slot
    // (4th launch). Dependencies: k_gate needs only k_comb; k_spmm needs the
    // full CSR build and stays last.
    k_comb  <<<1, 512>>>(wgcn, bgcn, wout, bout);
    k_zero  <<<(NN  + 255) / 256, 256>>>();
    k_degcnt<<<(NNZ + 255) / 256, 256>>>(ei, ew);

    // fused gates + z
    k_gate<<<BB * NN, dim3(32, 8)>>>(x, wg1, bg1, wg2, bg2, out);

    k_scan  <<<1, 1024>>>();
    k_fill  <<<(NNZ + 255) / 256, 256>>>(ei, ew);

    // gather
    size_t smem_bytes = (size_t)NN * 32 * sizeof(float);   // 128 KB
    cudaFuncSetAttribute(k_spmm, cudaFuncAttributeMaxDynamicSharedMemorySize,
                         (int)smem_bytes);
    k_spmm<<<2 * GG, 1024, smem_bytes>>>(out + OUT1_ELEMS);
}

// round 10
// speedup vs baseline: 1.8871x; 1.1774x over previous
#include <cuda_runtime.h>
#include <cstdint>

// ---------------- problem constants ----------------
#define BB   16
#define TT   34
#define TP   32          // T - DIL
#define NN   1000
#define CIN  32
#define DC   32
#define OC   64
#define EE   16000
#define NNZ  (EE + NN)   // edges + self loops = 17000
#define GG   (BB * TP)   // 512 graphs
#define NB   4           // nodes per k_gate block

#define OUT1_ELEMS ((size_t)BB * DC * NN * TP)        // 16,384,000

typedef unsigned long long u64c;

// ---------------- f32x2 packed helpers ----------------
__device__ __forceinline__ u64c fma2(u64c a, u64c b, u64c c) {
    u64c d;
    asm("fma.rn.f32x2 %0, %1, %2, %3;" : "=l"(d) : "l"(a), "l"(b), "l"(c));
    return d;
}
__device__ __forceinline__ float f2sum(u64c a) {
    return __int_as_float((int)(a & 0xffffffffULL)) +
           __int_as_float((int)(a >> 32));
}
__device__ __forceinline__ u64c pack2(float lo, float hi) {
    u64c r;
    asm("mov.b64 %0, {%1, %2};" : "=l"(r) : "f"(lo), "f"(hi));
    return r;
}
__device__ __forceinline__ float u64lo(u64c a) { return __int_as_float((int)(a & 0xffffffffULL)); }
__device__ __forceinline__ float u64hi(u64c a) { return __int_as_float((int)(a >> 32)); }

// ---------------- device scratch ----------------
__device__ float g_z[(size_t)GG * NN * OC];   // 131 MB: z = gated @ Wcomb^T
__device__ float g_wcomb[OC * DC];            // Wcomb[o][d] = sum_c wout[o][c] wgcn[c][d]
__device__ float g_ybias[OC];                 // bgcn @ wout^T + bout
__device__ int   g_off[NN + 1];
__device__ int2  g_csr[NNZ];                  // (src*128 byte offset, f32 val as int)

// ---------------- K_comb: combined weights (propagate/conv commute) --------
__global__ void k_comb(const float* __restrict__ wgcn, const float* __restrict__ bgcn,
                       const float* __restrict__ wout, const float* __restrict__ bout) {
    __shared__ float sg[CIN * DC];   // wgcn [c][d]
    __shared__ float so[OC * CIN];   // wout [o][c]
    __shared__ float sb[CIN];
    int tid = threadIdx.x;
    for (int f = tid; f < CIN * DC; f += blockDim.x) sg[f] = wgcn[f];
    for (int f = tid; f < OC * CIN; f += blockDim.x) so[f] = wout[f];
    if (tid < CIN) sb[tid] = bgcn[tid];
    __syncthreads();
    for (int f = tid; f < OC * DC; f += blockDim.x) {
        int o = f >> 5, d = f & 31;
        float s = 0.f;
#pragma unroll
        for (int c = 0; c < CIN; c++) s += so[o * CIN + c] * sg[c * DC + d];
        g_wcomb[f] = s;
    }
    if (tid < OC) {
        float s = bout[tid];
#pragma unroll
        for (int c = 0; c < CIN; c++) s += sb[c] * so[tid * CIN + c];
        g_ybias[tid] = s;
    }
}

// ---------------- K_build: fused CSR build (single block, smem atomics) ----
__global__ __launch_bounds__(1024) void k_build(const int* __restrict__ ei,
                                                const float* __restrict__ ew) {
    __shared__ float sdeg[NN];
    __shared__ int   scnt[NN];
    __shared__ int   ssc[1024];
    __shared__ int   scur[NN];
    int tid = threadIdx.x;

    for (int i = tid; i < NN; i += 1024) { sdeg[i] = 0.f; scnt[i] = 0; }
    __syncthreads();

    // degree + counts
    for (int i = tid; i < NNZ; i += 1024) {
        int d; float w;
        if (i < EE) { d = ei[EE + i]; w = ew[i]; }
        else        { d = i - EE;     w = 1.f;   }
        atomicAdd(&sdeg[d], w);
        atomicAdd(&scnt[d], 1);
    }
    __syncthreads();

    // exclusive scan over counts
    int v = (tid < NN) ? scnt[tid] : 0;
    ssc[tid] = v;
    __syncthreads();
    for (int off = 1; off < 1024; off <<= 1) {
        int tv = (tid >= off) ? ssc[tid - off] : 0;
        __syncthreads();
        ssc[tid] += tv;
        __syncthreads();
    }
    if (tid < NN) {
        int excl = ssc[tid] - v;
        scur[tid] = excl;
        g_off[tid] = excl;
    }
    if (tid == NN - 1) g_off[NN] = ssc[tid];
    __syncthreads();

    // fill normalized CSR
    for (int i = tid; i < NNZ; i += 1024) {
        int s, d; float w;
        if (i < EE) { s = ei[i]; d = ei[EE + i]; w = ew[i]; }
        else        { s = i - EE; d = s;         w = 1.f;   }
        float degs = sdeg[s], degd = sdeg[d];
        float dis_s = (degs > 0.f) ? rsqrtf(degs) : 0.f;
        float dis_d = (degd > 0.f) ? rsqrtf(degd) : 0.f;
        int p = atomicAdd(&scur[d], 1);
        g_csr[p] = make_int2(s * 128, __float_as_int(dis_s * w * dis_d));
    }
}

// ---------------- K_gate: fused gated conv + z, NB=4 nodes per block -------
// 256 threads (8 warps). Phase 1: warp wy owns o-quad {4wy..4wy+3}, t = lane;
// each weight ulonglong2 is loaded ONCE per (oo,c4) and feeds 4 nodes x 8 fma2
// (4x fewer weight broadcasts than 1-node blocks). gated stored per (nb) as a
// single conflict-free STS.128. Phase 2: thread (o = tid&63, ts = tid>>6)
// computes z for all 4 nodes with Wcomb row cached in regs (loaded once).
struct SmemGate {
    float4 xq[NB][8][34];                  // [nb][c4][t]
    float4 w1a[32][8], w1b[32][8];         // [o][c4]
    float4 w2a[32][8], w2b[32][8];
    float4 wcq[8][64];                     // [d4][o]
    float  gs[NB][32 * 36];                // gated [t][d], pitch 36
};

__global__ __launch_bounds__(256) void k_gate(
    const float* __restrict__ x,
    const float* __restrict__ wg1, const float* __restrict__ bg1,
    const float* __restrict__ wg2, const float* __restrict__ bg2,
    float* __restrict__ out1)
{
    extern __shared__ char smem_raw[];
    SmemGate& S = *(SmemGate*)smem_raw;

    int blk = blockIdx.x;                  // 4000 blocks
    int b  = blk / (NN / NB);
    int n0 = (blk - b * (NN / NB)) * NB;

    int tx = threadIdx.x;                  // 0..31 (t)
    int wy = threadIdx.y;                  // 0..7  (o-quad)
    int tid = wy * 32 + tx;

    // stage gate weights (flat f = o*32+c, 1024 per array)
    for (int f = tid; f < 32 * 32; f += 256) {
        float2 v1 = *(const float2*)(wg1 + f * 2);
        float2 v2 = *(const float2*)(wg2 + f * 2);
        ((float*)S.w1a)[f] = v1.x;
        ((float*)S.w1b)[f] = v1.y;
        ((float*)S.w2a)[f] = v2.x;
        ((float*)S.w2b)[f] = v2.y;
    }
    // stage Wcomb: flat f = (d4*64+o)*4+k  <-  wcomb[o*32 + d4*4 + k]
    for (int f = tid; f < 8 * 64 * 4; f += 256) {
        int k = f & 3, o = (f >> 2) & 63, d4 = f >> 8;
        ((float*)S.wcq)[f] = g_wcomb[o * 32 + d4 * 4 + k];
    }
    // stage x tiles: NB nodes x 34 t x 8 c4
    for (int f = tid; f < NB * 34 * 8; f += 256) {
        int nb = f / (34 * 8);
        int r  = f - nb * (34 * 8);
        int t = r >> 3, c4 = r & 7;
        S.xq[nb][c4][t] =
            *(const float4*)(x + ((size_t)(b * TT + t) * NN + (n0 + nb)) * CIN + c4 * 4);
    }
    __syncthreads();

    // ---- phase 1: gates ----
    {
        float bg1v[4], bg2v[4];
#pragma unroll
        for (int oo = 0; oo < 4; oo++) {
            bg1v[oo] = __ldg(bg1 + 4 * wy + oo);
            bg2v[oo] = __ldg(bg2 + 4 * wy + oo);
        }
        u64c a1[4][NB], a2[4][NB];
#pragma unroll
        for (int oo = 0; oo < 4; oo++)
#pragma unroll
            for (int nb = 0; nb < NB; nb++) { a1[oo][nb] = 0; a2[oo][nb] = 0; }

#pragma unroll
        for (int c4 = 0; c4 < 8; c4++) {
            ulonglong2 xa[NB], xb[NB];
#pragma unroll
            for (int nb = 0; nb < NB; nb++) {
                xa[nb] = *(const ulonglong2*)&S.xq[nb][c4][tx];
                xb[nb] = *(const ulonglong2*)&S.xq[nb][c4][tx + 2];
            }
#pragma unroll
            for (int oo = 0; oo < 4; oo++) {
                int o = 4 * wy + oo;
                ulonglong2 A1 = *(const ulonglong2*)&S.w1a[o][c4];
                ulonglong2 B1 = *(const ulonglong2*)&S.w1b[o][c4];
                ulonglong2 A2 = *(const ulonglong2*)&S.w2a[o][c4];
                ulonglong2 B2 = *(const ulonglong2*)&S.w2b[o][c4];
#pragma unroll
                for (int nb = 0; nb < NB; nb++) {
                    a1[oo][nb] = fma2(xa[nb].x, A1.x, a1[oo][nb]);
                    a1[oo][nb] = fma2(xa[nb].y, A1.y, a1[oo][nb]);
                    a1[oo][nb] = fma2(xb[nb].x, B1.x, a1[oo][nb]);
                    a1[oo][nb] = fma2(xb[nb].y, B1.y, a1[oo][nb]);
                    a2[oo][nb] = fma2(xa[nb].x, A2.x, a2[oo][nb]);
                    a2[oo][nb] = fma2(xa[nb].y, A2.y, a2[oo][nb]);
                    a2[oo][nb] = fma2(xb[nb].x, B2.x, a2[oo][nb]);
                    a2[oo][nb] = fma2(xb[nb].y, B2.y, a2[oo][nb]);
                }
            }
        }

#pragma unroll
        for (int nb = 0; nb < NB; nb++) {
            float4 gq;
#pragma unroll
            for (int oo = 0; oo < 4; oo++) {
                int o = 4 * wy + oo;
                float s1 = f2sum(a1[oo][nb]) + bg1v[oo];
                float s2 = f2sum(a2[oo][nb]) + bg2v[oo];
                float e1 = __expf(2.f * s1);
                float th = 1.f - __fdividef(2.f, e1 + 1.f);    // tanh, inf-safe
                float sg = __fdividef(1.f, 1.f + __expf(-s2)); // sigmoid
                float gated = th * sg;
                out1[((size_t)(b * DC + o) * NN + (n0 + nb)) * TP + tx] = gated;
                (&gq.x)[oo] = gated;
            }
            // single conflict-free STS.128 (pitch 36: phases hit distinct banks)
            *(float4*)&S.gs[nb][tx * 36 + 4 * wy] = gq;
        }
    }
    __syncthreads();

    // ---- phase 2: z[t][o] = sum_d gated[t][d] * Wcomb[o][d] ----
    {
        int o  = tid & 63;
        int ts = tid >> 6;          // 0..3
        ulonglong2 wr[8];
#pragma unroll
        for (int d4 = 0; d4 < 8; d4++)
            wr[d4] = *(const ulonglong2*)&S.wcq[d4][o];
#pragma unroll
        for (int nb = 0; nb < NB; nb++) {
            const float* gsn = S.gs[nb];
#pragma unroll
            for (int it = 0; it < 8; it++) {
                int t = ts * 8 + it;
                const ulonglong2* gp = (const ulonglong2*)(gsn + t * 36);
                u64c za = 0, zb = 0;
#pragma unroll
                for (int d4 = 0; d4 < 8; d4++) {
                    ulonglong2 g2 = gp[d4];
                    za = fma2(g2.x, wr[d4].x, za);
                    zb = fma2(g2.y, wr[d4].y, zb);
                }
                g_z[((size_t)(b * TP + t) * NN + (n0 + nb)) * OC + o] =
                    f2sum(za) + f2sum(zb);
            }
        }
    }
}

// ---------------- K_spmm: pure gather  y[g,i,:] = sum_e val*z[src,:] + ybias
// 1024 blocks = (graph g, channel-half). z half-slab (1000x32 = 128 KB) staged
// in dynamic SMEM. Warp = 4 subgroups x 8 lanes: subgroup walks one row's edge
// list, each lane accumulates a float4 of channels as two packed fma2 chains.
__global__ __launch_bounds__(1024, 1) void k_spmm(float* __restrict__ y)
{
    extern __shared__ float z_s[];            // [N][32]
    int bx = blockIdx.x;
    int g = bx >> 1, half = bx & 1;
    int tid = threadIdx.x;

    for (int f = tid; f < NN * 8; f += 1024) {
        int n = f >> 3, c4 = f & 7;
        ((float4*)z_s)[f] =
            *(const float4*)(g_z + ((size_t)g * NN + n) * OC + half * 32 + c4 * 4);
    }
    __syncthreads();

    int warp = tid >> 5;
    int lane = tid & 31;
    int sub  = lane >> 3;                     // 0..3 row subgroup
    int c4   = lane & 7;                      // float4 channel group in half
    float4 yb4 = *(const float4*)(g_ybias + half * 32 + c4 * 4);
    const char* zb = (const char*)z_s + c4 * 16;

    for (int i0 = warp * 4 + sub; i0 < NN + 3; i0 += 128) {
        int i = i0;
        bool valid = (i < NN);
        int r0 = 0, r1 = 0;
        if (valid) { r0 = g_off[i]; r1 = g_off[i + 1]; }
        u64c a0 = pack2(yb4.x, yb4.y);
        u64c a1 = pack2(yb4.z, yb4.w);
#pragma unroll 2
        for (int e = r0; e < r1; e++) {
            int2 ev = __ldg(&g_csr[e]);       // uniform within subgroup
            float v = __int_as_float(ev.y);
            u64c vv = pack2(v, v);
            ulonglong2 zz = *(const ulonglong2*)(zb + ev.x);
            a0 = fma2(zz.x, vv, a0);
            a1 = fma2(zz.y, vv, a1);
        }
        if (valid) {
            float4 r;
            r.x = u64lo(a0); r.y = u64hi(a0);
            r.z = u64lo(a1); r.w = u64hi(a1);
            *(float4*)(y + ((size_t)g * NN + i) * OC + half * 32 + c4 * 4) = r;
        }
    }
}

// ---------------- launcher ----------------
extern "C" void kernel_launch(void* const* d_in, const int* in_sizes, int n_in,
                              void* d_out, int out_size)
{
    const float* x    = (const float*)d_in[0];
    const int*   ei   = (const int*)  d_in[1];
    const float* ew   = (const float*)d_in[2];
    const float* wg1  = (const float*)d_in[3];
    const float* bg1  = (const float*)d_in[4];
    const float* wg2  = (const float*)d_in[5];
    const float* bg2  = (const float*)d_in[6];
    const float* wgcn = (const float*)d_in[7];
    const float* bgcn = (const float*)d_in[8];
    const float* wout = (const float*)d_in[9];
    const float* bout = (const float*)d_in[10];
    float* out = (float*)d_out;

    // 4 launches total: k_spmm is launch #4 (ncu capture slot)
    k_comb <<<1, 512>>>(wgcn, bgcn, wout, bout);
    k_build<<<1, 1024>>>(ei, ew);

    size_t gate_smem = sizeof(SmemGate);      // ~60 KB
    cudaFuncSetAttribute(k_gate, cudaFuncAttributeMaxDynamicSharedMemorySize,
                         (int)gate_smem);
    k_gate<<<BB * (NN / NB), dim3(32, 8), gate_smem>>>(x, wg1, bg1, wg2, bg2, out);

    size_t smem_bytes = (size_t)NN * 32 * sizeof(float);   // 128 KB
    cudaFuncSetAttribute(k_spmm, cudaFuncAttributeMaxDynamicSharedMemorySize,
                         (int)smem_bytes);
    k_spmm<<<2 * GG, 1024, smem_bytes>>>(out + OUT1_ELEMS);
}